// round 10
// baseline (speedup 1.0000x reference)
#include <cuda_runtime.h>
#include <cuda_fp16.h>
#include <math.h>
#include <stdint.h>

// ---------------------------------------------------------------------------
// Problem constants
// ---------------------------------------------------------------------------
#define BB   32
#define SS   128
#define HH   1024
#define G4   4096
#define VV   32000
#define MBS  4096                      // B*S
#define LOGITS 131072000LL             // B*S*V

// ---------------------------------------------------------------------------
// Device scratch
// ---------------------------------------------------------------------------
__device__ __half    g_emb [MBS * HH];             // 8 MB   [m][H] fp16
__device__ __half    g_xp  [2L * MBS * G4];        // 64 MB  [dir][m][4H] fp16
__device__ __half    g_comb[MBS * 2 * HH];         // 16 MB  [m][2H] fp16
__device__ uint32_t  g_wihp[2L * 512 * G4];        // 16 MB  packed fp16 pairs [k2][N]
__device__ uint32_t  g_wtp [1024L * VV];           // 128 MB packed fp16 pairs [k2][N]
__device__ uint32_t  g_whht[2L * G4 * 512];        // 16 MB  packed fp16 pairs [col][k2]
__device__ __half    g_h   [2 * 2 * BB * HH];      // [dir][pingpong][b][H]
__device__ unsigned  g_bar [2 * SS];               // per-dir barrier counters

// ---------------------------------------------------------------------------
// Helpers
// ---------------------------------------------------------------------------
__device__ __forceinline__ float4 ldcg4(const float4* p) {
    float4 v;
    asm volatile("ld.global.cg.v4.f32 {%0,%1,%2,%3}, [%4];"
                 : "=f"(v.x), "=f"(v.y), "=f"(v.z), "=f"(v.w) : "l"(p));
    return v;
}
__device__ __forceinline__ float sigm(float x) { return 1.f / (1.f + expf(-x)); }

__device__ __forceinline__ void mma_fp16(float* d, const uint32_t* a, const uint32_t* b) {
    asm volatile(
        "mma.sync.aligned.m16n8k16.row.col.f32.f16.f16.f32 "
        "{%0,%1,%2,%3},{%4,%5,%6,%7},{%8,%9},{%0,%1,%2,%3};"
        : "+f"(d[0]), "+f"(d[1]), "+f"(d[2]), "+f"(d[3])
        : "r"(a[0]), "r"(a[1]), "r"(a[2]), "r"(a[3]), "r"(b[0]), "r"(b[1]));
}

__device__ __forceinline__ void cpasync16(uint32_t dst, const void* src) {
    asm volatile("cp.async.cg.shared.global [%0], [%1], 16;" :: "r"(dst), "l"(src));
}
__device__ __forceinline__ uint32_t smem_u32(const void* p) {
    uint32_t a;
    asm("{ .reg .u64 t; cvta.to.shared.u64 t, %1; cvt.u32.u64 %0, t; }" : "=r"(a) : "l"(p));
    return a;
}

// ---------------------------------------------------------------------------
// Kernel: embedding gather -> fp16
// ---------------------------------------------------------------------------
__global__ void embed_kernel(const int* __restrict__ x, const float* __restrict__ embed) {
    int m = blockIdx.x;
    int idx = x[m];
    const float4* src = (const float4*)(embed + (size_t)idx * HH);
    __half2* dst = (__half2*)(g_emb + (size_t)m * HH);
    float4 v = src[threadIdx.x];
    dst[threadIdx.x * 2]     = __floats2half2_rn(v.x, v.y);
    dst[threadIdx.x * 2 + 1] = __floats2half2_rn(v.z, v.w);
}

// ---------------------------------------------------------------------------
// Kernel: all weight prep in ONE launch.
// Blocks [0, NPACKB): flat k-pair packing of W_ih_f, W_ih_b, W_out.
// Blocks [NPACKB, NPACKB+NTRB): tiled transpose-pack of W_hh -> [col][k2].
// ---------------------------------------------------------------------------
#define NPACKB 4096
#define NTRB   4096     // 2 dirs * 16 k2-tiles * 128 col-tiles

__global__ __launch_bounds__(256) void prep_kernel(
    const float* __restrict__ Wihf, const float* __restrict__ Wihb,
    const float* __restrict__ Wout,
    const float* __restrict__ Whhf, const float* __restrict__ Whhb)
{
    __shared__ float ts[64][33];
    int tid = threadIdx.x;

    if (blockIdx.x < NPACKB) {
        const size_t S1 = 512L * G4;          // wih_f words
        const size_t S2 = 2 * S1;             // + wih_b
        const size_t TOT = S2 + 1024L * VV;   // + wt
        for (size_t i = (size_t)blockIdx.x * 256 + tid; i < TOT;
             i += (size_t)NPACKB * 256) {
            const float* src; uint32_t* dst; size_t off; int N;
            if (i < S1)       { src = Wihf; dst = g_wihp;      off = i;      N = G4; }
            else if (i < S2)  { src = Wihb; dst = g_wihp + S1; off = i - S1; N = G4; }
            else              { src = Wout; dst = g_wtp;       off = i - S2; N = VV; }
            size_t kk = off / (size_t)N, col = off - kk * N;
            __half2 h = __floats2half2_rn(src[(2 * kk) * (size_t)N + col],
                                          src[(2 * kk + 1) * (size_t)N + col]);
            dst[off] = *(uint32_t*)&h;
        }
    } else {
        int t   = blockIdx.x - NPACKB;
        int dir = t >> 11;
        int rem = t & 2047;
        int bx = rem & 127, by = rem >> 7;    // col tile (32), k2 tile (32)
        const float* src = dir ? Whhb : Whhf;
        int tx = tid & 31, ty = tid >> 5;
        int r0 = by * 64, c0 = bx * 32;
#pragma unroll
        for (int i = 0; i < 8; i++)
            ts[ty + 8 * i][tx] = src[(size_t)(r0 + ty + 8 * i) * G4 + c0 + tx];
        __syncthreads();
#pragma unroll
        for (int i = 0; i < 4; i++) {
            int colL = ty + 8 * i, k2L = tx;
            __half2 h = __floats2half2_rn(ts[2 * k2L][colL], ts[2 * k2L + 1][colL]);
            g_whht[(size_t)dir * G4 * 512 + (size_t)(c0 + colL) * 512 + by * 32 + k2L]
                = *(uint32_t*)&h;
        }
    }
}

// ---------------------------------------------------------------------------
// Kernel: fp16 GEMM  C[M,N] = A[M,K] @ B[K,N] + bias[N]   (B packed k-pairs)
// CTA tile 128x256, K-chunk 32, 4-stage cp.async pipeline, 512 thr,
// 16 warps as 2(wm) x 8(wn), warp tile 64x32 -> 4 warps/SMSP for latency
// hiding (R8 ncu: occ 12.4%, issue 19.6% with 8 warps was the binder).
// A: fp16 row-major [M][K]. Bp: uint32 [K/2][N]. half_out: store fp16.
// Requires M%128==0, N%256==0, K%32==0.
// ---------------------------------------------------------------------------
#define STAGES 4
#define APITCH 20
#define BPITCH 264
#define ASTG   (128 * APITCH)
#define BSTG   (16 * BPITCH)
#define STGW   (ASTG + BSTG)
#define GSMEM  (STAGES * STGW * 4)

__global__ __launch_bounds__(512, 1) void gemm_fp16(
    const __half* __restrict__ A, const uint32_t* __restrict__ Bp,
    const float* __restrict__ bias, void* __restrict__ Cv,
    int M, int N, int K, int tiles_m, int half_out)
{
    extern __shared__ __align__(16) uint32_t smw[];
    uint32_t sb = smem_u32(smw);

    int tid = threadIdx.x, lane = tid & 31, warp = tid >> 5;
    int gid = lane >> 2, tq = lane & 3;
    int wm = warp >> 3, wn = warp & 7;

    int mt = blockIdx.x % tiles_m, nt = blockIdx.x / tiles_m;
    size_t m0 = (size_t)mt * 128, n0 = (size_t)nt * 256;
    int CH = K >> 5;

    // cp.async assignment: A 512 ops (1/thread), B 1024 ops (2/thread)
    const __half* asrc; uint32_t adst;
    {
        int r = tid >> 2, seg = tid & 3;
        asrc = A + (m0 + r) * (size_t)K + seg * 8;
        adst = (r * APITCH + seg * 4) * 4;
    }
    const uint32_t* bsrc[2]; uint32_t bdst[2];
#pragma unroll
    for (int i = 0; i < 2; i++) {
        int id = tid + 512 * i;
        int kk = id >> 6, seg = id & 63;
        bsrc[i] = Bp + (size_t)kk * N + n0 + seg * 4;
        bdst[i] = (ASTG + kk * BPITCH + seg * 4) * 4;
    }

    float acc[4][4][4];
#pragma unroll
    for (int i = 0; i < 4; i++)
#pragma unroll
        for (int j = 0; j < 4; j++)
#pragma unroll
            for (int e = 0; e < 4; e++) acc[i][j][e] = 0.f;

#define ISSUE_CHUNK(c, s) {                                                  \
    uint32_t stb = sb + (uint32_t)(s) * (STGW * 4);                          \
    int k0h = (c) << 5;                                                      \
    size_t k0w = (size_t)((c) << 4) * N;                                     \
    cpasync16(stb + adst, asrc + k0h);                                       \
    cpasync16(stb + bdst[0], bsrc[0] + k0w);                                 \
    cpasync16(stb + bdst[1], bsrc[1] + k0w);                                 \
}

    ISSUE_CHUNK(0, 0);
    asm volatile("cp.async.commit_group;");
    ISSUE_CHUNK(1, 1);
    asm volatile("cp.async.commit_group;");
    ISSUE_CHUNK(2, 2);
    asm volatile("cp.async.commit_group;");

    for (int c = 0; c < CH; c++) {
        asm volatile("cp.async.wait_group 2;");
        __syncthreads();
        if (c + 3 < CH) { int s = (c + 3) & (STAGES - 1); ISSUE_CHUNK(c + 3, s); }
        asm volatile("cp.async.commit_group;");

        const uint32_t* sA = smw + (c & (STAGES - 1)) * STGW;
        const uint32_t* sB = sA + ASTG;
#pragma unroll
        for (int h = 0; h < 2; h++) {
            int kk = h * 8;
            uint32_t a[4][4], b[4][2];
#pragma unroll
            for (int mi = 0; mi < 4; mi++) {
                int r = wm * 64 + mi * 16 + gid;
                a[mi][0] = sA[r * APITCH + kk + tq];
                a[mi][1] = sA[(r + 8) * APITCH + kk + tq];
                a[mi][2] = sA[r * APITCH + kk + tq + 4];
                a[mi][3] = sA[(r + 8) * APITCH + kk + tq + 4];
            }
#pragma unroll
            for (int ni = 0; ni < 4; ni++) {
                int cc = wn * 32 + ni * 8 + gid;
                b[ni][0] = sB[(kk + tq) * BPITCH + cc];
                b[ni][1] = sB[(kk + tq + 4) * BPITCH + cc];
            }
#pragma unroll
            for (int mi = 0; mi < 4; mi++)
#pragma unroll
                for (int ni = 0; ni < 4; ni++)
                    mma_fp16(acc[mi][ni], a[mi], b[ni]);
        }
    }

    // epilogue: add bias; store fp32 (logits) or fp16 (xp)
#pragma unroll
    for (int mi = 0; mi < 4; mi++) {
#pragma unroll
        for (int ni = 0; ni < 4; ni++) {
            size_t r = m0 + wm * 64 + mi * 16 + gid;
            size_t c = n0 + wn * 32 + ni * 8 + 2 * tq;
            float2 bv = *(const float2*)(bias + c);
            float v00 = acc[mi][ni][0] + bv.x, v01 = acc[mi][ni][1] + bv.y;
            float v10 = acc[mi][ni][2] + bv.x, v11 = acc[mi][ni][3] + bv.y;
            if (half_out) {
                __half* Ch = (__half*)Cv;
                *(__half2*)(Ch + r * (size_t)N + c)       = __floats2half2_rn(v00, v01);
                *(__half2*)(Ch + (r + 8) * (size_t)N + c) = __floats2half2_rn(v10, v11);
            } else {
                float* Cf = (float*)Cv;
                *(float2*)(Cf + r * (size_t)N + c)       = make_float2(v00, v01);
                *(float2*)(Cf + (r + 8) * (size_t)N + c) = make_float2(v10, v11);
            }
        }
    }
}

// ---------------------------------------------------------------------------
// Grid barrier: per-direction (64 CTAs), tight spin, self-resetting
// ---------------------------------------------------------------------------
__device__ __forceinline__ void gbar(int dir, int idx, int cid) {
    __threadfence();
    __syncthreads();
    if (threadIdx.x == 0) {
        unsigned* ctr = g_bar + dir * SS;
        unsigned a = atomicAdd(&ctr[idx], 1u);
        if (a + 1u < 64u) {
            while (((volatile unsigned*)ctr)[idx] < 64u) { }
        }
        if (cid == 0 && idx > 0) ((volatile unsigned*)ctr)[idx - 1] = 0u;
    }
    __syncthreads();
}

// ---------------------------------------------------------------------------
// Kernel: persistent bidirectional LSTM recurrence.
// W_hh slice SMEM-resident (loaded once); h via global ping-pong (ld.cg).
// ---------------------------------------------------------------------------
#define HPITCH 516
#define WPITCH 516
#define SW_WORDS (64 * WPITCH)          // 33024
#define H_WORDS  (32 * HPITCH)          // 16512
#define LSMEM ((SW_WORDS + H_WORDS + 32 * 68 + 512 + 64) * 4)

__global__ __launch_bounds__(256, 1) void lstm_kernel(
    const float* __restrict__ bhh_f, const float* __restrict__ bhh_b,
    float* __restrict__ out, int has_states)
{
    extern __shared__ uint32_t smu[];
    uint32_t* sW    = smu;                             // [64][WPITCH]
    uint32_t* h32   = smu + SW_WORDS;                  // [32][HPITCH]
    float* g_s      = (float*)(smu + SW_WORDS + H_WORDS);  // [32][68]
    float* c_s      = g_s + 32 * 68;                   // [512]
    float* bias_s   = c_s + 512;                       // [64]

    int dir = blockIdx.x >> 6;
    int cid = blockIdx.x & 63;
    int j0  = cid * 16;
    const float* bh = dir ? bhh_b : bhh_f;
    const __half* xp = g_xp + (size_t)dir * MBS * G4;
    __half* hbuf = g_h + (size_t)dir * 2 * BB * HH;

    int tid = threadIdx.x;
    int lane = tid & 31, warp = tid >> 5;
    int gid = lane >> 2, tq = lane & 3;
    int gate = warp & 3, kh = warp >> 2;

    // one-time: load W slice into SMEM (coalesced from transposed layout)
    {
        const uint32_t* Wt = g_whht + (size_t)dir * G4 * 512;
        for (int idx = tid; idx < 64 * 128; idx += 256) {
            int col = idx >> 7, seg = idx & 127;
            int gcol = (col >> 4) * 1024 + j0 + (col & 15);
            float4 v = *(const float4*)(Wt + (size_t)gcol * 512 + seg * 4);
            *(float4*)(sW + col * WPITCH + seg * 4) = v;
        }
    }
    for (int i = tid; i < 512; i += 256) c_s[i] = 0.f;
    if (tid < 64) bias_s[tid] = bh[(tid >> 4) * HH + j0 + (tid & 15)];
    for (int i = cid * 256 + tid; i < BB * HH; i += 64 * 256) hbuf[i] = __float2half(0.f);
    gbar(dir, 0, cid);

    int b0 = tid >> 4, jj = tid & 15;

    for (int step = 0; step < SS; step++) {
        int tseq = dir ? (SS - 1 - step) : step;
        int cur = step & 1, nxt = cur ^ 1;
        const __half* hg = hbuf + cur * BB * HH;

        // early xp prefetch (independent of this step's h)
        __half xr0[4], xr1[4];
        {
            const __half* x0 = xp + (size_t)(b0 * SS + tseq) * G4 + j0 + jj;
            const __half* x1 = xp + (size_t)((b0 + 16) * SS + tseq) * G4 + j0 + jj;
#pragma unroll
            for (int q = 0; q < 4; q++) { xr0[q] = x0[q * 1024]; xr1[q] = x1[q * 1024]; }
        }

        // copy h (fp16) -> SMEM, L1 bypass
        for (int idx = tid; idx < 4096; idx += 256) {
            int r = idx >> 7, seg = idx & 127;
            float4 v = ldcg4((const float4*)hg + r * 128 + seg);
            *(float4*)(h32 + r * HPITCH + seg * 4) = v;
        }
        __syncthreads();

        float acc[2][2][4];
#pragma unroll
        for (int i = 0; i < 2; i++)
#pragma unroll
            for (int j = 0; j < 2; j++)
#pragma unroll
                for (int e = 0; e < 4; e++) acc[i][j][e] = 0.f;

        int colb = gate * 16 + gid;
        int kend = kh * 256 + 256;
#pragma unroll 8
        for (int kb2 = kh * 256; kb2 < kend; kb2 += 8) {
            uint32_t a[2][4];
#pragma unroll
            for (int mi = 0; mi < 2; mi++) {
                int r = mi * 16 + gid;
                a[mi][0] = h32[r * HPITCH + kb2 + tq];
                a[mi][1] = h32[(r + 8) * HPITCH + kb2 + tq];
                a[mi][2] = h32[r * HPITCH + kb2 + tq + 4];
                a[mi][3] = h32[(r + 8) * HPITCH + kb2 + tq + 4];
            }
#pragma unroll
            for (int ni = 0; ni < 2; ni++) {
                uint32_t bf[2];
                const uint32_t* wc = sW + (colb + ni * 8) * WPITCH + kb2;
                bf[0] = wc[tq];
                bf[1] = wc[tq + 4];
                mma_fp16(acc[0][ni], a[0], bf);
                mma_fp16(acc[1][ni], a[1], bf);
            }
        }

        // partials: kh=0 stores, kh=1 accumulates
        float* gp = g_s + gate * 16;
        if (kh == 0) {
#pragma unroll
            for (int mi = 0; mi < 2; mi++)
#pragma unroll
                for (int ni = 0; ni < 2; ni++) {
                    int r = mi * 16 + gid, c = ni * 8 + 2 * tq;
                    gp[r * 68 + c]           = acc[mi][ni][0];
                    gp[r * 68 + c + 1]       = acc[mi][ni][1];
                    gp[(r + 8) * 68 + c]     = acc[mi][ni][2];
                    gp[(r + 8) * 68 + c + 1] = acc[mi][ni][3];
                }
        }
        __syncthreads();
        if (kh == 1) {
#pragma unroll
            for (int mi = 0; mi < 2; mi++)
#pragma unroll
                for (int ni = 0; ni < 2; ni++) {
                    int r = mi * 16 + gid, c = ni * 8 + 2 * tq;
                    gp[r * 68 + c]           += acc[mi][ni][0];
                    gp[r * 68 + c + 1]       += acc[mi][ni][1];
                    gp[(r + 8) * 68 + c]     += acc[mi][ni][2];
                    gp[(r + 8) * 68 + c + 1] += acc[mi][ni][3];
                }
        }
        __syncthreads();

        // elementwise LSTM update
        __half* hn = hbuf + nxt * BB * HH;
#pragma unroll
        for (int half = 0; half < 2; half++) {
            int b = b0 + half * 16;
            int it = b * 16 + jj;
            const __half* xr = half ? xr1 : xr0;
            float gq[4];
#pragma unroll
            for (int q = 0; q < 4; q++)
                gq[q] = g_s[b * 68 + q * 16 + jj] + __half2float(xr[q]) + bias_s[q * 16 + jj];
            float iv = sigm(gq[0]);
            float fv = sigm(gq[1]);
            float gv = tanhf(gq[2]);
            float ov = sigm(gq[3]);
            float c = fv * c_s[it] + iv * gv;
            float h = ov * tanhf(c);
            c_s[it] = c;
            hn[b * HH + j0 + jj] = __float2half(h);
            g_comb[((size_t)(b * SS + tseq)) * 2 * HH + dir * HH + j0 + jj] = __float2half(h);
            if (has_states && step == SS - 1) {
                size_t base = LOGITS + (size_t)dir * 2 * BB * HH;
                out[base + b * HH + j0 + jj] = h;            // hT
                out[base + BB * HH + b * HH + j0 + jj] = c;  // cT
            }
        }
        if (step < SS - 1) gbar(dir, step + 1, cid);
        else __syncthreads();
    }
    if (cid == 0 && threadIdx.x == 0)
        ((volatile unsigned*)(g_bar + dir * SS))[SS - 1] = 0u;
}

// ---------------------------------------------------------------------------
// Launch
// ---------------------------------------------------------------------------
extern "C" void kernel_launch(void* const* d_in, const int* in_sizes, int n_in,
                              void* d_out, int out_size) {
    const int*   x      = (const int*)d_in[0];
    const float* embed  = (const float*)d_in[1];
    const float* W_ih_f = (const float*)d_in[2];
    const float* b_ih_f = (const float*)d_in[3];
    const float* W_hh_f = (const float*)d_in[4];
    const float* b_hh_f = (const float*)d_in[5];
    const float* W_ih_b = (const float*)d_in[6];
    const float* b_ih_b = (const float*)d_in[7];
    const float* W_hh_b = (const float*)d_in[8];
    const float* b_hh_b = (const float*)d_in[9];
    const float* W_out  = (const float*)d_in[10];
    const float* b_out  = (const float*)d_in[11];
    float* out = (float*)d_out;

    void *pe, *pxp, *pcomb, *pwih, *pwt;
    cudaGetSymbolAddress(&pe, g_emb);
    cudaGetSymbolAddress(&pxp, g_xp);
    cudaGetSymbolAddress(&pcomb, g_comb);
    cudaGetSymbolAddress(&pwih, g_wihp);
    cudaGetSymbolAddress(&pwt, g_wtp);
    __half*   emb  = (__half*)pe;
    __half*   xp   = (__half*)pxp;
    __half*   comb = (__half*)pcomb;
    uint32_t* wih  = (uint32_t*)pwih;
    uint32_t* wt   = (uint32_t*)pwt;

    cudaFuncSetAttribute(gemm_fp16, cudaFuncAttributeMaxDynamicSharedMemorySize, GSMEM);
    cudaFuncSetAttribute(lstm_kernel, cudaFuncAttributeMaxDynamicSharedMemorySize, LSMEM);

    // 0: embedding
    embed_kernel<<<MBS, 256>>>(x, embed);
    // 1: all weight prep (packs + W_hh transpose)
    prep_kernel<<<NPACKB + NTRB, 256>>>(W_ih_f, W_ih_b, W_out, W_hh_f, W_hh_b);
    // 2,3: input projections -> xp (fp16)
    gemm_fp16<<<32 * 16, 512, GSMEM>>>(emb, wih, b_ih_f, xp, MBS, G4, HH, 32, 1);
    gemm_fp16<<<32 * 16, 512, GSMEM>>>(emb, wih + 512L * G4, b_ih_b,
                                       xp + (size_t)MBS * G4, MBS, G4, HH, 32, 1);
    // 4: recurrence
    long long need = LOGITS + 4LL * BB * HH;
    int has_states = ((long long)out_size >= need) ? 1 : 0;
    lstm_kernel<<<128, 256, LSMEM>>>(b_hh_f, b_hh_b, out, has_states);
    // 5: output projection -> logits (fp32)
    gemm_fp16<<<32 * 125, 512, GSMEM>>>(comb, wt, b_out, out, MBS, VV, 2 * HH, 32, 0);
}

// round 13
// speedup vs baseline: 1.0640x; 1.0640x over previous
#include <cuda_runtime.h>
#include <cuda_fp16.h>
#include <math.h>
#include <stdint.h>

// ---------------------------------------------------------------------------
// Problem constants
// ---------------------------------------------------------------------------
#define BB   32
#define SS   128
#define HH   1024
#define G4   4096
#define VV   32000
#define MBS  4096                      // B*S
#define LOGITS 131072000LL             // B*S*V

// ---------------------------------------------------------------------------
// Device scratch
// ---------------------------------------------------------------------------
__device__ __half    g_emb [MBS * HH];             // 8 MB   [m][H] fp16
__device__ __half    g_xp  [2L * MBS * G4];        // 64 MB  [dir][m][4H] fp16
__device__ __half    g_comb[MBS * 2 * HH];         // 16 MB  [m][2H] fp16
__device__ uint32_t  g_wihp[2L * 512 * G4];        // 16 MB  packed fp16 pairs [k2][N]
__device__ uint32_t  g_wtp [1024L * VV];           // 128 MB packed fp16 pairs [k2][N]
__device__ uint32_t  g_whht[2L * G4 * 512];        // 16 MB  packed fp16 pairs [col][k2]
__device__ __half    g_h   [2 * 2 * BB * HH];      // [dir][pingpong][b][H]
__device__ unsigned  g_bar [2 * SS];               // per-dir barrier counters

// ---------------------------------------------------------------------------
// Helpers
// ---------------------------------------------------------------------------
__device__ __forceinline__ float4 ldcg4(const float4* p) {
    float4 v;
    asm volatile("ld.global.cg.v4.f32 {%0,%1,%2,%3}, [%4];"
                 : "=f"(v.x), "=f"(v.y), "=f"(v.z), "=f"(v.w) : "l"(p));
    return v;
}
__device__ __forceinline__ float sigm(float x) { return 1.f / (1.f + expf(-x)); }

__device__ __forceinline__ void mma_fp16(float* d, const uint32_t* a, const uint32_t* b) {
    asm volatile(
        "mma.sync.aligned.m16n8k16.row.col.f32.f16.f16.f32 "
        "{%0,%1,%2,%3},{%4,%5,%6,%7},{%8,%9},{%0,%1,%2,%3};"
        : "+f"(d[0]), "+f"(d[1]), "+f"(d[2]), "+f"(d[3])
        : "r"(a[0]), "r"(a[1]), "r"(a[2]), "r"(a[3]), "r"(b[0]), "r"(b[1]));
}

__device__ __forceinline__ void cpasync16(uint32_t dst, const void* src) {
    asm volatile("cp.async.cg.shared.global [%0], [%1], 16;" :: "r"(dst), "l"(src));
}
__device__ __forceinline__ uint32_t smem_u32(const void* p) {
    uint32_t a;
    asm("{ .reg .u64 t; cvta.to.shared.u64 t, %1; cvt.u32.u64 %0, t; }" : "=r"(a) : "l"(p));
    return a;
}

// ---------------------------------------------------------------------------
// Kernel: embedding gather -> fp16
// ---------------------------------------------------------------------------
__global__ void embed_kernel(const int* __restrict__ x, const float* __restrict__ embed) {
    int m = blockIdx.x;
    int idx = x[m];
    const float4* src = (const float4*)(embed + (size_t)idx * HH);
    __half2* dst = (__half2*)(g_emb + (size_t)m * HH);
    float4 v = src[threadIdx.x];
    dst[threadIdx.x * 2]     = __floats2half2_rn(v.x, v.y);
    dst[threadIdx.x * 2 + 1] = __floats2half2_rn(v.z, v.w);
}

// ---------------------------------------------------------------------------
// Kernel: all weight prep in ONE launch.
// ---------------------------------------------------------------------------
#define NPACKB 4096
#define NTRB   4096     // 2 dirs * 16 k2-tiles * 128 col-tiles

__global__ __launch_bounds__(256) void prep_kernel(
    const float* __restrict__ Wihf, const float* __restrict__ Wihb,
    const float* __restrict__ Wout,
    const float* __restrict__ Whhf, const float* __restrict__ Whhb)
{
    __shared__ float ts[64][33];
    int tid = threadIdx.x;

    if (blockIdx.x < NPACKB) {
        const size_t S1 = 512L * G4;
        const size_t S2 = 2 * S1;
        const size_t TOT = S2 + 1024L * VV;
        for (size_t i = (size_t)blockIdx.x * 256 + tid; i < TOT;
             i += (size_t)NPACKB * 256) {
            const float* src; uint32_t* dst; size_t off; int N;
            if (i < S1)       { src = Wihf; dst = g_wihp;      off = i;      N = G4; }
            else if (i < S2)  { src = Wihb; dst = g_wihp + S1; off = i - S1; N = G4; }
            else              { src = Wout; dst = g_wtp;       off = i - S2; N = VV; }
            size_t kk = off / (size_t)N, col = off - kk * N;
            __half2 h = __floats2half2_rn(src[(2 * kk) * (size_t)N + col],
                                          src[(2 * kk + 1) * (size_t)N + col]);
            dst[off] = *(uint32_t*)&h;
        }
    } else {
        int t   = blockIdx.x - NPACKB;
        int dir = t >> 11;
        int rem = t & 2047;
        int bx = rem & 127, by = rem >> 7;
        const float* src = dir ? Whhb : Whhf;
        int tx = tid & 31, ty = tid >> 5;
        int r0 = by * 64, c0 = bx * 32;
#pragma unroll
        for (int i = 0; i < 8; i++)
            ts[ty + 8 * i][tx] = src[(size_t)(r0 + ty + 8 * i) * G4 + c0 + tx];
        __syncthreads();
#pragma unroll
        for (int i = 0; i < 4; i++) {
            int colL = ty + 8 * i, k2L = tx;
            __half2 h = __floats2half2_rn(ts[2 * k2L][colL], ts[2 * k2L + 1][colL]);
            g_whht[(size_t)dir * G4 * 512 + (size_t)(c0 + colL) * 512 + by * 32 + k2L]
                = *(uint32_t*)&h;
        }
    }
}

// ---------------------------------------------------------------------------
// Kernel: fp16 GEMM  C[M,N] = A[M,K] @ B[K,N] + bias[N]   (B packed k-pairs)
// CTA tile 128x128, K-chunk 32, 3-stage cp.async, 256 thr, 8 warps as
// 2(wm) x 4(wn), warp tile 64x32, __launch_bounds__(256,2) -> 2 CTAs/SM.
// Two independent barrier domains per SM interleave LDS/MMA phases
// (R9 evidence: one lockstep CTA leaves tensor at ~40%).
// Requires M%128==0, N%128==0, K%32==0.
// ---------------------------------------------------------------------------
#define STAGES 3
#define APITCH 20                 // uint32 words per A row (16 data + 4 pad)
#define BPITCH 136                // uint32 words per B row (128 data + 8 pad)
#define ASTG   (128 * APITCH)     // 2560 words
#define BSTG   (16 * BPITCH)      // 2176 words
#define STGW   (ASTG + BSTG)      // 4736 words / stage
#define GSMEM  (STAGES * STGW * 4)   // 56832 B -> 2 CTAs/SM

__global__ __launch_bounds__(256, 2) void gemm_fp16(
    const __half* __restrict__ A, const uint32_t* __restrict__ Bp,
    const float* __restrict__ bias, void* __restrict__ Cv,
    int M, int N, int K, int tiles_m, int half_out)
{
    extern __shared__ __align__(16) uint32_t smw[];
    uint32_t sb = smem_u32(smw);

    int tid = threadIdx.x, lane = tid & 31, warp = tid >> 5;
    int gid = lane >> 2, tq = lane & 3;
    int wm = warp >> 2, wn = warp & 3;

    int mt = blockIdx.x % tiles_m, nt = blockIdx.x / tiles_m;
    size_t m0 = (size_t)mt * 128, n0 = (size_t)nt * 128;
    int CH = K >> 5;

    // cp.async: A 512 ops (2/thread), B 512 ops (2/thread)
    const __half* asrc[2]; uint32_t adst[2];
#pragma unroll
    for (int i = 0; i < 2; i++) {
        int id = tid + 256 * i;
        int r = id >> 2, seg = id & 3;
        asrc[i] = A + (m0 + r) * (size_t)K + seg * 8;
        adst[i] = (r * APITCH + seg * 4) * 4;
    }
    const uint32_t* bsrc[2]; uint32_t bdst[2];
#pragma unroll
    for (int i = 0; i < 2; i++) {
        int id = tid + 256 * i;
        int kk = id >> 5, seg = id & 31;
        bsrc[i] = Bp + (size_t)kk * N + n0 + seg * 4;
        bdst[i] = (ASTG + kk * BPITCH + seg * 4) * 4;
    }

    float acc[4][4][4];
#pragma unroll
    for (int i = 0; i < 4; i++)
#pragma unroll
        for (int j = 0; j < 4; j++)
#pragma unroll
            for (int e = 0; e < 4; e++) acc[i][j][e] = 0.f;

#define ISSUE_CHUNK(c, s) {                                                  \
    uint32_t stb = sb + (uint32_t)(s) * (STGW * 4);                          \
    int k0h = (c) << 5;                                                      \
    size_t k0w = (size_t)((c) << 4) * N;                                     \
    cpasync16(stb + adst[0], asrc[0] + k0h);                                 \
    cpasync16(stb + adst[1], asrc[1] + k0h);                                 \
    cpasync16(stb + bdst[0], bsrc[0] + k0w);                                 \
    cpasync16(stb + bdst[1], bsrc[1] + k0w);                                 \
}

    ISSUE_CHUNK(0, 0);
    asm volatile("cp.async.commit_group;");
    ISSUE_CHUNK(1, 1);
    asm volatile("cp.async.commit_group;");

    for (int c = 0; c < CH; c++) {
        asm volatile("cp.async.wait_group 1;");
        __syncthreads();
        if (c + 2 < CH) { int s = (c + 2) % STAGES; ISSUE_CHUNK(c + 2, s); }
        asm volatile("cp.async.commit_group;");

        const uint32_t* sA = smw + (c % STAGES) * STGW;
        const uint32_t* sB = sA + ASTG;
#pragma unroll
        for (int h = 0; h < 2; h++) {
            int kk = h * 8;
            uint32_t a[4][4], b[4][2];
#pragma unroll
            for (int mi = 0; mi < 4; mi++) {
                int r = wm * 64 + mi * 16 + gid;
                a[mi][0] = sA[r * APITCH + kk + tq];
                a[mi][1] = sA[(r + 8) * APITCH + kk + tq];
                a[mi][2] = sA[r * APITCH + kk + tq + 4];
                a[mi][3] = sA[(r + 8) * APITCH + kk + tq + 4];
            }
#pragma unroll
            for (int ni = 0; ni < 4; ni++) {
                int cc = wn * 32 + ni * 8 + gid;
                b[ni][0] = sB[(kk + tq) * BPITCH + cc];
                b[ni][1] = sB[(kk + tq + 4) * BPITCH + cc];
            }
#pragma unroll
            for (int mi = 0; mi < 4; mi++)
#pragma unroll
                for (int ni = 0; ni < 4; ni++)
                    mma_fp16(acc[mi][ni], a[mi], b[ni]);
        }
    }

    // epilogue: add bias; store fp32 (logits) or fp16 (xp)
#pragma unroll
    for (int mi = 0; mi < 4; mi++) {
#pragma unroll
        for (int ni = 0; ni < 4; ni++) {
            size_t r = m0 + wm * 64 + mi * 16 + gid;
            size_t c = n0 + wn * 32 + ni * 8 + 2 * tq;
            float2 bv = *(const float2*)(bias + c);
            float v00 = acc[mi][ni][0] + bv.x, v01 = acc[mi][ni][1] + bv.y;
            float v10 = acc[mi][ni][2] + bv.x, v11 = acc[mi][ni][3] + bv.y;
            if (half_out) {
                __half* Ch = (__half*)Cv;
                *(__half2*)(Ch + r * (size_t)N + c)       = __floats2half2_rn(v00, v01);
                *(__half2*)(Ch + (r + 8) * (size_t)N + c) = __floats2half2_rn(v10, v11);
            } else {
                float* Cf = (float*)Cv;
                *(float2*)(Cf + r * (size_t)N + c)       = make_float2(v00, v01);
                *(float2*)(Cf + (r + 8) * (size_t)N + c) = make_float2(v10, v11);
            }
        }
    }
}

// ---------------------------------------------------------------------------
// Grid barrier: per-direction (64 CTAs), tight spin, self-resetting
// ---------------------------------------------------------------------------
__device__ __forceinline__ void gbar(int dir, int idx, int cid) {
    __threadfence();
    __syncthreads();
    if (threadIdx.x == 0) {
        unsigned* ctr = g_bar + dir * SS;
        unsigned a = atomicAdd(&ctr[idx], 1u);
        if (a + 1u < 64u) {
            while (((volatile unsigned*)ctr)[idx] < 64u) { }
        }
        if (cid == 0 && idx > 0) ((volatile unsigned*)ctr)[idx - 1] = 0u;
    }
    __syncthreads();
}

// ---------------------------------------------------------------------------
// Kernel: persistent bidirectional LSTM recurrence (unchanged from R8 best).
// ---------------------------------------------------------------------------
#define HPITCH 516
#define WPITCH 516
#define SW_WORDS (64 * WPITCH)
#define H_WORDS  (32 * HPITCH)
#define LSMEM ((SW_WORDS + H_WORDS + 32 * 68 + 512 + 64) * 4)

__global__ __launch_bounds__(256, 1) void lstm_kernel(
    const float* __restrict__ bhh_f, const float* __restrict__ bhh_b,
    float* __restrict__ out, int has_states)
{
    extern __shared__ uint32_t smu[];
    uint32_t* sW    = smu;                             // [64][WPITCH]
    uint32_t* h32   = smu + SW_WORDS;                  // [32][HPITCH]
    float* g_s      = (float*)(smu + SW_WORDS + H_WORDS);  // [32][68]
    float* c_s      = g_s + 32 * 68;                   // [512]
    float* bias_s   = c_s + 512;                       // [64]

    int dir = blockIdx.x >> 6;
    int cid = blockIdx.x & 63;
    int j0  = cid * 16;
    const float* bh = dir ? bhh_b : bhh_f;
    const __half* xp = g_xp + (size_t)dir * MBS * G4;
    __half* hbuf = g_h + (size_t)dir * 2 * BB * HH;

    int tid = threadIdx.x;
    int lane = tid & 31, warp = tid >> 5;
    int gid = lane >> 2, tq = lane & 3;
    int gate = warp & 3, kh = warp >> 2;

    {
        const uint32_t* Wt = g_whht + (size_t)dir * G4 * 512;
        for (int idx = tid; idx < 64 * 128; idx += 256) {
            int col = idx >> 7, seg = idx & 127;
            int gcol = (col >> 4) * 1024 + j0 + (col & 15);
            float4 v = *(const float4*)(Wt + (size_t)gcol * 512 + seg * 4);
            *(float4*)(sW + col * WPITCH + seg * 4) = v;
        }
    }
    for (int i = tid; i < 512; i += 256) c_s[i] = 0.f;
    if (tid < 64) bias_s[tid] = bh[(tid >> 4) * HH + j0 + (tid & 15)];
    for (int i = cid * 256 + tid; i < BB * HH; i += 64 * 256) hbuf[i] = __float2half(0.f);
    gbar(dir, 0, cid);

    int b0 = tid >> 4, jj = tid & 15;

    for (int step = 0; step < SS; step++) {
        int tseq = dir ? (SS - 1 - step) : step;
        int cur = step & 1, nxt = cur ^ 1;
        const __half* hg = hbuf + cur * BB * HH;

        __half xr0[4], xr1[4];
        {
            const __half* x0 = xp + (size_t)(b0 * SS + tseq) * G4 + j0 + jj;
            const __half* x1 = xp + (size_t)((b0 + 16) * SS + tseq) * G4 + j0 + jj;
#pragma unroll
            for (int q = 0; q < 4; q++) { xr0[q] = x0[q * 1024]; xr1[q] = x1[q * 1024]; }
        }

        for (int idx = tid; idx < 4096; idx += 256) {
            int r = idx >> 7, seg = idx & 127;
            float4 v = ldcg4((const float4*)hg + r * 128 + seg);
            *(float4*)(h32 + r * HPITCH + seg * 4) = v;
        }
        __syncthreads();

        float acc[2][2][4];
#pragma unroll
        for (int i = 0; i < 2; i++)
#pragma unroll
            for (int j = 0; j < 2; j++)
#pragma unroll
                for (int e = 0; e < 4; e++) acc[i][j][e] = 0.f;

        int colb = gate * 16 + gid;
        int kend = kh * 256 + 256;
#pragma unroll 8
        for (int kb2 = kh * 256; kb2 < kend; kb2 += 8) {
            uint32_t a[2][4];
#pragma unroll
            for (int mi = 0; mi < 2; mi++) {
                int r = mi * 16 + gid;
                a[mi][0] = h32[r * HPITCH + kb2 + tq];
                a[mi][1] = h32[(r + 8) * HPITCH + kb2 + tq];
                a[mi][2] = h32[r * HPITCH + kb2 + tq + 4];
                a[mi][3] = h32[(r + 8) * HPITCH + kb2 + tq + 4];
            }
#pragma unroll
            for (int ni = 0; ni < 2; ni++) {
                uint32_t bf[2];
                const uint32_t* wc = sW + (colb + ni * 8) * WPITCH + kb2;
                bf[0] = wc[tq];
                bf[1] = wc[tq + 4];
                mma_fp16(acc[0][ni], a[0], bf);
                mma_fp16(acc[1][ni], a[1], bf);
            }
        }

        float* gp = g_s + gate * 16;
        if (kh == 0) {
#pragma unroll
            for (int mi = 0; mi < 2; mi++)
#pragma unroll
                for (int ni = 0; ni < 2; ni++) {
                    int r = mi * 16 + gid, c = ni * 8 + 2 * tq;
                    gp[r * 68 + c]           = acc[mi][ni][0];
                    gp[r * 68 + c + 1]       = acc[mi][ni][1];
                    gp[(r + 8) * 68 + c]     = acc[mi][ni][2];
                    gp[(r + 8) * 68 + c + 1] = acc[mi][ni][3];
                }
        }
        __syncthreads();
        if (kh == 1) {
#pragma unroll
            for (int mi = 0; mi < 2; mi++)
#pragma unroll
                for (int ni = 0; ni < 2; ni++) {
                    int r = mi * 16 + gid, c = ni * 8 + 2 * tq;
                    gp[r * 68 + c]           += acc[mi][ni][0];
                    gp[r * 68 + c + 1]       += acc[mi][ni][1];
                    gp[(r + 8) * 68 + c]     += acc[mi][ni][2];
                    gp[(r + 8) * 68 + c + 1] += acc[mi][ni][3];
                }
        }
        __syncthreads();

        __half* hn = hbuf + nxt * BB * HH;
#pragma unroll
        for (int half = 0; half < 2; half++) {
            int b = b0 + half * 16;
            int it = b * 16 + jj;
            const __half* xr = half ? xr1 : xr0;
            float gq[4];
#pragma unroll
            for (int q = 0; q < 4; q++)
                gq[q] = g_s[b * 68 + q * 16 + jj] + __half2float(xr[q]) + bias_s[q * 16 + jj];
            float iv = sigm(gq[0]);
            float fv = sigm(gq[1]);
            float gv = tanhf(gq[2]);
            float ov = sigm(gq[3]);
            float c = fv * c_s[it] + iv * gv;
            float h = ov * tanhf(c);
            c_s[it] = c;
            hn[b * HH + j0 + jj] = __float2half(h);
            g_comb[((size_t)(b * SS + tseq)) * 2 * HH + dir * HH + j0 + jj] = __float2half(h);
            if (has_states && step == SS - 1) {
                size_t base = LOGITS + (size_t)dir * 2 * BB * HH;
                out[base + b * HH + j0 + jj] = h;            // hT
                out[base + BB * HH + b * HH + j0 + jj] = c;  // cT
            }
        }
        if (step < SS - 1) gbar(dir, step + 1, cid);
        else __syncthreads();
    }
    if (cid == 0 && threadIdx.x == 0)
        ((volatile unsigned*)(g_bar + dir * SS))[SS - 1] = 0u;
}

// ---------------------------------------------------------------------------
// Launch
// ---------------------------------------------------------------------------
extern "C" void kernel_launch(void* const* d_in, const int* in_sizes, int n_in,
                              void* d_out, int out_size) {
    const int*   x      = (const int*)d_in[0];
    const float* embed  = (const float*)d_in[1];
    const float* W_ih_f = (const float*)d_in[2];
    const float* b_ih_f = (const float*)d_in[3];
    const float* W_hh_f = (const float*)d_in[4];
    const float* b_hh_f = (const float*)d_in[5];
    const float* W_ih_b = (const float*)d_in[6];
    const float* b_ih_b = (const float*)d_in[7];
    const float* W_hh_b = (const float*)d_in[8];
    const float* b_hh_b = (const float*)d_in[9];
    const float* W_out  = (const float*)d_in[10];
    const float* b_out  = (const float*)d_in[11];
    float* out = (float*)d_out;

    void *pe, *pxp, *pcomb, *pwih, *pwt;
    cudaGetSymbolAddress(&pe, g_emb);
    cudaGetSymbolAddress(&pxp, g_xp);
    cudaGetSymbolAddress(&pcomb, g_comb);
    cudaGetSymbolAddress(&pwih, g_wihp);
    cudaGetSymbolAddress(&pwt, g_wtp);
    __half*   emb  = (__half*)pe;
    __half*   xp   = (__half*)pxp;
    __half*   comb = (__half*)pcomb;
    uint32_t* wih  = (uint32_t*)pwih;
    uint32_t* wt   = (uint32_t*)pwt;

    cudaFuncSetAttribute(gemm_fp16, cudaFuncAttributeMaxDynamicSharedMemorySize, GSMEM);
    cudaFuncSetAttribute(lstm_kernel, cudaFuncAttributeMaxDynamicSharedMemorySize, LSMEM);

    // 0: embedding
    embed_kernel<<<MBS, 256>>>(x, embed);
    // 1: all weight prep (packs + W_hh transpose)
    prep_kernel<<<NPACKB + NTRB, 256>>>(W_ih_f, W_ih_b, W_out, W_hh_f, W_hh_b);
    // 2,3: input projections -> xp (fp16), N-tile 128 -> 32x32 tiles
    gemm_fp16<<<32 * 32, 256, GSMEM>>>(emb, wih, b_ih_f, xp, MBS, G4, HH, 32, 1);
    gemm_fp16<<<32 * 32, 256, GSMEM>>>(emb, wih + 512L * G4, b_ih_b,
                                       xp + (size_t)MBS * G4, MBS, G4, HH, 32, 1);
    // 4: recurrence
    long long need = LOGITS + 4LL * BB * HH;
    int has_states = ((long long)out_size >= need) ? 1 : 0;
    lstm_kernel<<<128, 256, LSMEM>>>(b_hh_f, b_hh_b, out, has_states);
    // 5: output projection -> logits (fp32), 32 x 250 tiles
    gemm_fp16<<<32 * 250, 256, GSMEM>>>(comb, wt, b_out, out, MBS, VV, 2 * HH, 32, 0);
}

// round 14
// speedup vs baseline: 1.1568x; 1.0872x over previous
#include <cuda_runtime.h>
#include <cuda_fp16.h>
#include <math.h>
#include <stdint.h>

// ---------------------------------------------------------------------------
// Problem constants
// ---------------------------------------------------------------------------
#define BB   32
#define SS   128
#define HH   1024
#define G4   4096
#define VV   32000
#define MBS  4096                      // B*S
#define LOGITS 131072000LL             // B*S*V

// ---------------------------------------------------------------------------
// Device scratch
// ---------------------------------------------------------------------------
__device__ __half    g_emb [MBS * HH];             // 8 MB   [m][H] fp16
__device__ __half    g_xp  [2L * MBS * G4];        // 64 MB  [dir][m][4H] fp16
__device__ __half    g_comb[MBS * 2 * HH];         // 16 MB  [m][2H] fp16
__device__ uint32_t  g_wihp[2L * 512 * G4];        // 16 MB  packed fp16 pairs [k2][N]
__device__ uint32_t  g_wtp [1024L * VV];           // 128 MB packed fp16 pairs [k2][N]
__device__ uint32_t  g_whht[2L * G4 * 512];        // 16 MB  packed fp16 pairs [col][k2]
__device__ __half    g_h   [2 * 2 * BB * HH];      // [dir][pingpong][b][H]
__device__ unsigned  g_bar [2 * SS];               // per-dir barrier counters

// ---------------------------------------------------------------------------
// Helpers
// ---------------------------------------------------------------------------
__device__ __forceinline__ float4 ldcg4(const float4* p) {
    float4 v;
    asm volatile("ld.global.cg.v4.f32 {%0,%1,%2,%3}, [%4];"
                 : "=f"(v.x), "=f"(v.y), "=f"(v.z), "=f"(v.w) : "l"(p));
    return v;
}
__device__ __forceinline__ float sigm(float x) { return 1.f / (1.f + expf(-x)); }

__device__ __forceinline__ void mma_fp16(float* d, const uint32_t* a, const uint32_t* b) {
    asm volatile(
        "mma.sync.aligned.m16n8k16.row.col.f32.f16.f16.f32 "
        "{%0,%1,%2,%3},{%4,%5,%6,%7},{%8,%9},{%0,%1,%2,%3};"
        : "+f"(d[0]), "+f"(d[1]), "+f"(d[2]), "+f"(d[3])
        : "r"(a[0]), "r"(a[1]), "r"(a[2]), "r"(a[3]), "r"(b[0]), "r"(b[1]));
}

__device__ __forceinline__ void cpasync16(uint32_t dst, const void* src) {
    asm volatile("cp.async.cg.shared.global [%0], [%1], 16;" :: "r"(dst), "l"(src));
}
__device__ __forceinline__ uint32_t smem_u32(const void* p) {
    uint32_t a;
    asm("{ .reg .u64 t; cvta.to.shared.u64 t, %1; cvt.u32.u64 %0, t; }" : "=r"(a) : "l"(p));
    return a;
}

// ---------------------------------------------------------------------------
// Kernel: embedding gather -> fp16
// ---------------------------------------------------------------------------
__global__ void embed_kernel(const int* __restrict__ x, const float* __restrict__ embed) {
    int m = blockIdx.x;
    int idx = x[m];
    const float4* src = (const float4*)(embed + (size_t)idx * HH);
    __half2* dst = (__half2*)(g_emb + (size_t)m * HH);
    float4 v = src[threadIdx.x];
    dst[threadIdx.x * 2]     = __floats2half2_rn(v.x, v.y);
    dst[threadIdx.x * 2 + 1] = __floats2half2_rn(v.z, v.w);
}

// ---------------------------------------------------------------------------
// Kernel: all weight prep in ONE launch.
// ---------------------------------------------------------------------------
#define NPACKB 4096
#define NTRB   4096     // 2 dirs * 16 k2-tiles * 128 col-tiles

__global__ __launch_bounds__(256) void prep_kernel(
    const float* __restrict__ Wihf, const float* __restrict__ Wihb,
    const float* __restrict__ Wout,
    const float* __restrict__ Whhf, const float* __restrict__ Whhb)
{
    __shared__ float ts[64][33];
    int tid = threadIdx.x;

    if (blockIdx.x < NPACKB) {
        const size_t S1 = 512L * G4;
        const size_t S2 = 2 * S1;
        const size_t TOT = S2 + 1024L * VV;
        for (size_t i = (size_t)blockIdx.x * 256 + tid; i < TOT;
             i += (size_t)NPACKB * 256) {
            const float* src; uint32_t* dst; size_t off; int N;
            if (i < S1)       { src = Wihf; dst = g_wihp;      off = i;      N = G4; }
            else if (i < S2)  { src = Wihb; dst = g_wihp + S1; off = i - S1; N = G4; }
            else              { src = Wout; dst = g_wtp;       off = i - S2; N = VV; }
            size_t kk = off / (size_t)N, col = off - kk * N;
            __half2 h = __floats2half2_rn(src[(2 * kk) * (size_t)N + col],
                                          src[(2 * kk + 1) * (size_t)N + col]);
            dst[off] = *(uint32_t*)&h;
        }
    } else {
        int t   = blockIdx.x - NPACKB;
        int dir = t >> 11;
        int rem = t & 2047;
        int bx = rem & 127, by = rem >> 7;
        const float* src = dir ? Whhb : Whhf;
        int tx = tid & 31, ty = tid >> 5;
        int r0 = by * 64, c0 = bx * 32;
#pragma unroll
        for (int i = 0; i < 8; i++)
            ts[ty + 8 * i][tx] = src[(size_t)(r0 + ty + 8 * i) * G4 + c0 + tx];
        __syncthreads();
#pragma unroll
        for (int i = 0; i < 4; i++) {
            int colL = ty + 8 * i, k2L = tx;
            __half2 h = __floats2half2_rn(ts[2 * k2L][colL], ts[2 * k2L + 1][colL]);
            g_whht[(size_t)dir * G4 * 512 + (size_t)(c0 + colL) * 512 + by * 32 + k2L]
                = *(uint32_t*)&h;
        }
    }
}

// ---------------------------------------------------------------------------
// Kernel: fp16 GEMM  C[M,N] = A[M,K] @ B[K,N] + bias[N]   (B packed k-pairs)
// CTA tile 128x128, K-chunk 64 (half the barriers of K32), 3-stage cp.async,
// 256 thr, 8 warps as 2(wm) x 4(wn), warp tile 64x32, 2 CTAs/SM.
// Fragment DOUBLE BUFFERING: h+1's A/B fragments load during h's MMAs,
// removing the LDS->MMA dependency stall (R13: tensor 47.7%, issue 28%,
// nothing saturated => stall-bound).
// Requires M%128==0, N%128==0, K%64==0.
// ---------------------------------------------------------------------------
#define STAGES 3
#define APITCH 36                 // words per A row (32 data + 4 pad)
#define BPITCH 136                // words per B row (128 data + 8 pad)
#define ASTG   (128 * APITCH)     // 4608 words
#define BSTG   (32 * BPITCH)      // 4352 words
#define STGW   (ASTG + BSTG)      // 8960 words / stage
#define GSMEM  (STAGES * STGW * 4)   // 107520 B -> 2 CTAs/SM (210 KB/SM)

__global__ __launch_bounds__(256, 2) void gemm_fp16(
    const __half* __restrict__ A, const uint32_t* __restrict__ Bp,
    const float* __restrict__ bias, void* __restrict__ Cv,
    int M, int N, int K, int tiles_m, int half_out)
{
    extern __shared__ __align__(16) uint32_t smw[];
    uint32_t sb = smem_u32(smw);

    int tid = threadIdx.x, lane = tid & 31, warp = tid >> 5;
    int gid = lane >> 2, tq = lane & 3;
    int wm = warp >> 2, wn = warp & 3;

    int mt = blockIdx.x % tiles_m, nt = blockIdx.x / tiles_m;
    size_t m0 = (size_t)mt * 128, n0 = (size_t)nt * 128;
    int CH = K >> 6;

    // cp.async bases: A 1024 ops (4/thread, row-stride 32 between ops),
    //                 B 1024 ops (4/thread, k2-stride 8 between ops)
    const __half*   a_src = A + (m0 + (tid >> 3)) * (size_t)K + (tid & 7) * 8;
    const uint32_t* b_src = Bp + (size_t)(tid >> 5) * N + n0 + (tid & 31) * 4;
    uint32_t a_dst = ((tid >> 3) * APITCH + (tid & 7) * 4) * 4;
    uint32_t b_dst = (ASTG + (tid >> 5) * BPITCH + (tid & 31) * 4) * 4;

    float acc[4][4][4];
#pragma unroll
    for (int i = 0; i < 4; i++)
#pragma unroll
        for (int j = 0; j < 4; j++)
#pragma unroll
            for (int e = 0; e < 4; e++) acc[i][j][e] = 0.f;

#define ISSUE_CHUNK(c, s) {                                                   \
    uint32_t stb = sb + (uint32_t)(s) * (STGW * 4);                           \
    int k0h = (c) << 6;                                                       \
    size_t k0w = (size_t)((c) << 5) * N;                                      \
    _Pragma("unroll")                                                         \
    for (int i = 0; i < 4; i++)                                               \
        cpasync16(stb + a_dst + i * (32 * APITCH * 4),                        \
                  a_src + k0h + (size_t)(32 * i) * K);                        \
    _Pragma("unroll")                                                         \
    for (int i = 0; i < 4; i++)                                               \
        cpasync16(stb + b_dst + i * (8 * BPITCH * 4),                         \
                  b_src + k0w + (size_t)(8 * i) * N);                         \
}

#define LDFRAGS(buf, h) {                                                     \
    int kk = (h) * 8;                                                         \
    _Pragma("unroll")                                                         \
    for (int mi = 0; mi < 4; mi++) {                                          \
        int r = wm * 64 + mi * 16 + gid;                                      \
        af[buf][mi][0] = sA[r * APITCH + kk + tq];                            \
        af[buf][mi][1] = sA[(r + 8) * APITCH + kk + tq];                      \
        af[buf][mi][2] = sA[r * APITCH + kk + tq + 4];                        \
        af[buf][mi][3] = sA[(r + 8) * APITCH + kk + tq + 4];                  \
    }                                                                         \
    _Pragma("unroll")                                                         \
    for (int ni = 0; ni < 4; ni++) {                                          \
        int cc = wn * 32 + ni * 8 + gid;                                      \
        bf[buf][ni][0] = sB[(kk + tq) * BPITCH + cc];                         \
        bf[buf][ni][1] = sB[(kk + tq + 4) * BPITCH + cc];                     \
    }                                                                         \
}

    ISSUE_CHUNK(0, 0);
    asm volatile("cp.async.commit_group;");
    ISSUE_CHUNK(1, 1);
    asm volatile("cp.async.commit_group;");

    for (int c = 0; c < CH; c++) {
        asm volatile("cp.async.wait_group 1;");
        __syncthreads();
        if (c + 2 < CH) { int s = (c + 2) % STAGES; ISSUE_CHUNK(c + 2, s); }
        asm volatile("cp.async.commit_group;");

        const uint32_t* sA = smw + (c % STAGES) * STGW;
        const uint32_t* sB = sA + ASTG;

        uint32_t af[2][4][4], bf[2][4][2];
        LDFRAGS(0, 0);
#pragma unroll
        for (int h = 0; h < 4; h++) {
            int cb = h & 1;
            if (h < 3) LDFRAGS(cb ^ 1, h + 1);
#pragma unroll
            for (int mi = 0; mi < 4; mi++)
#pragma unroll
                for (int ni = 0; ni < 4; ni++)
                    mma_fp16(acc[mi][ni], af[cb][mi], bf[cb][ni]);
        }
    }

    // epilogue: add bias; store fp32 (logits) or fp16 (xp)
#pragma unroll
    for (int mi = 0; mi < 4; mi++) {
#pragma unroll
        for (int ni = 0; ni < 4; ni++) {
            size_t r = m0 + wm * 64 + mi * 16 + gid;
            size_t c = n0 + wn * 32 + ni * 8 + 2 * tq;
            float2 bv = *(const float2*)(bias + c);
            float v00 = acc[mi][ni][0] + bv.x, v01 = acc[mi][ni][1] + bv.y;
            float v10 = acc[mi][ni][2] + bv.x, v11 = acc[mi][ni][3] + bv.y;
            if (half_out) {
                __half* Ch = (__half*)Cv;
                *(__half2*)(Ch + r * (size_t)N + c)       = __floats2half2_rn(v00, v01);
                *(__half2*)(Ch + (r + 8) * (size_t)N + c) = __floats2half2_rn(v10, v11);
            } else {
                float* Cf = (float*)Cv;
                *(float2*)(Cf + r * (size_t)N + c)       = make_float2(v00, v01);
                *(float2*)(Cf + (r + 8) * (size_t)N + c) = make_float2(v10, v11);
            }
        }
    }
}

// ---------------------------------------------------------------------------
// Grid barrier: per-direction (64 CTAs), tight spin, self-resetting
// ---------------------------------------------------------------------------
__device__ __forceinline__ void gbar(int dir, int idx, int cid) {
    __threadfence();
    __syncthreads();
    if (threadIdx.x == 0) {
        unsigned* ctr = g_bar + dir * SS;
        unsigned a = atomicAdd(&ctr[idx], 1u);
        if (a + 1u < 64u) {
            while (((volatile unsigned*)ctr)[idx] < 64u) { }
        }
        if (cid == 0 && idx > 0) ((volatile unsigned*)ctr)[idx - 1] = 0u;
    }
    __syncthreads();
}

// ---------------------------------------------------------------------------
// Kernel: persistent bidirectional LSTM recurrence (unchanged from R13).
// ---------------------------------------------------------------------------
#define HPITCH 516
#define WPITCH 516
#define SW_WORDS (64 * WPITCH)
#define H_WORDS  (32 * HPITCH)
#define LSMEM ((SW_WORDS + H_WORDS + 32 * 68 + 512 + 64) * 4)

__global__ __launch_bounds__(256, 1) void lstm_kernel(
    const float* __restrict__ bhh_f, const float* __restrict__ bhh_b,
    float* __restrict__ out, int has_states)
{
    extern __shared__ uint32_t smu[];
    uint32_t* sW    = smu;                             // [64][WPITCH]
    uint32_t* h32   = smu + SW_WORDS;                  // [32][HPITCH]
    float* g_s      = (float*)(smu + SW_WORDS + H_WORDS);  // [32][68]
    float* c_s      = g_s + 32 * 68;                   // [512]
    float* bias_s   = c_s + 512;                       // [64]

    int dir = blockIdx.x >> 6;
    int cid = blockIdx.x & 63;
    int j0  = cid * 16;
    const float* bh = dir ? bhh_b : bhh_f;
    const __half* xp = g_xp + (size_t)dir * MBS * G4;
    __half* hbuf = g_h + (size_t)dir * 2 * BB * HH;

    int tid = threadIdx.x;
    int lane = tid & 31, warp = tid >> 5;
    int gid = lane >> 2, tq = lane & 3;
    int gate = warp & 3, kh = warp >> 2;

    {
        const uint32_t* Wt = g_whht + (size_t)dir * G4 * 512;
        for (int idx = tid; idx < 64 * 128; idx += 256) {
            int col = idx >> 7, seg = idx & 127;
            int gcol = (col >> 4) * 1024 + j0 + (col & 15);
            float4 v = *(const float4*)(Wt + (size_t)gcol * 512 + seg * 4);
            *(float4*)(sW + col * WPITCH + seg * 4) = v;
        }
    }
    for (int i = tid; i < 512; i += 256) c_s[i] = 0.f;
    if (tid < 64) bias_s[tid] = bh[(tid >> 4) * HH + j0 + (tid & 15)];
    for (int i = cid * 256 + tid; i < BB * HH; i += 64 * 256) hbuf[i] = __float2half(0.f);
    gbar(dir, 0, cid);

    int b0 = tid >> 4, jj = tid & 15;

    for (int step = 0; step < SS; step++) {
        int tseq = dir ? (SS - 1 - step) : step;
        int cur = step & 1, nxt = cur ^ 1;
        const __half* hg = hbuf + cur * BB * HH;

        __half xr0[4], xr1[4];
        {
            const __half* x0 = xp + (size_t)(b0 * SS + tseq) * G4 + j0 + jj;
            const __half* x1 = xp + (size_t)((b0 + 16) * SS + tseq) * G4 + j0 + jj;
#pragma unroll
            for (int q = 0; q < 4; q++) { xr0[q] = x0[q * 1024]; xr1[q] = x1[q * 1024]; }
        }

        for (int idx = tid; idx < 4096; idx += 256) {
            int r = idx >> 7, seg = idx & 127;
            float4 v = ldcg4((const float4*)hg + r * 128 + seg);
            *(float4*)(h32 + r * HPITCH + seg * 4) = v;
        }
        __syncthreads();

        float acc[2][2][4];
#pragma unroll
        for (int i = 0; i < 2; i++)
#pragma unroll
            for (int j = 0; j < 2; j++)
#pragma unroll
                for (int e = 0; e < 4; e++) acc[i][j][e] = 0.f;

        int colb = gate * 16 + gid;
        int kend = kh * 256 + 256;
#pragma unroll 8
        for (int kb2 = kh * 256; kb2 < kend; kb2 += 8) {
            uint32_t a[2][4];
#pragma unroll
            for (int mi = 0; mi < 2; mi++) {
                int r = mi * 16 + gid;
                a[mi][0] = h32[r * HPITCH + kb2 + tq];
                a[mi][1] = h32[(r + 8) * HPITCH + kb2 + tq];
                a[mi][2] = h32[r * HPITCH + kb2 + tq + 4];
                a[mi][3] = h32[(r + 8) * HPITCH + kb2 + tq + 4];
            }
#pragma unroll
            for (int ni = 0; ni < 2; ni++) {
                uint32_t bfr[2];
                const uint32_t* wc = sW + (colb + ni * 8) * WPITCH + kb2;
                bfr[0] = wc[tq];
                bfr[1] = wc[tq + 4];
                mma_fp16(acc[0][ni], a[0], bfr);
                mma_fp16(acc[1][ni], a[1], bfr);
            }
        }

        float* gp = g_s + gate * 16;
        if (kh == 0) {
#pragma unroll
            for (int mi = 0; mi < 2; mi++)
#pragma unroll
                for (int ni = 0; ni < 2; ni++) {
                    int r = mi * 16 + gid, c = ni * 8 + 2 * tq;
                    gp[r * 68 + c]           = acc[mi][ni][0];
                    gp[r * 68 + c + 1]       = acc[mi][ni][1];
                    gp[(r + 8) * 68 + c]     = acc[mi][ni][2];
                    gp[(r + 8) * 68 + c + 1] = acc[mi][ni][3];
                }
        }
        __syncthreads();
        if (kh == 1) {
#pragma unroll
            for (int mi = 0; mi < 2; mi++)
#pragma unroll
                for (int ni = 0; ni < 2; ni++) {
                    int r = mi * 16 + gid, c = ni * 8 + 2 * tq;
                    gp[r * 68 + c]           += acc[mi][ni][0];
                    gp[r * 68 + c + 1]       += acc[mi][ni][1];
                    gp[(r + 8) * 68 + c]     += acc[mi][ni][2];
                    gp[(r + 8) * 68 + c + 1] += acc[mi][ni][3];
                }
        }
        __syncthreads();

        __half* hn = hbuf + nxt * BB * HH;
#pragma unroll
        for (int half = 0; half < 2; half++) {
            int b = b0 + half * 16;
            int it = b * 16 + jj;
            const __half* xr = half ? xr1 : xr0;
            float gq[4];
#pragma unroll
            for (int q = 0; q < 4; q++)
                gq[q] = g_s[b * 68 + q * 16 + jj] + __half2float(xr[q]) + bias_s[q * 16 + jj];
            float iv = sigm(gq[0]);
            float fv = sigm(gq[1]);
            float gv = tanhf(gq[2]);
            float ov = sigm(gq[3]);
            float c = fv * c_s[it] + iv * gv;
            float h = ov * tanhf(c);
            c_s[it] = c;
            hn[b * HH + j0 + jj] = __float2half(h);
            g_comb[((size_t)(b * SS + tseq)) * 2 * HH + dir * HH + j0 + jj] = __float2half(h);
            if (has_states && step == SS - 1) {
                size_t base = LOGITS + (size_t)dir * 2 * BB * HH;
                out[base + b * HH + j0 + jj] = h;            // hT
                out[base + BB * HH + b * HH + j0 + jj] = c;  // cT
            }
        }
        if (step < SS - 1) gbar(dir, step + 1, cid);
        else __syncthreads();
    }
    if (cid == 0 && threadIdx.x == 0)
        ((volatile unsigned*)(g_bar + dir * SS))[SS - 1] = 0u;
}

// ---------------------------------------------------------------------------
// Launch
// ---------------------------------------------------------------------------
extern "C" void kernel_launch(void* const* d_in, const int* in_sizes, int n_in,
                              void* d_out, int out_size) {
    const int*   x      = (const int*)d_in[0];
    const float* embed  = (const float*)d_in[1];
    const float* W_ih_f = (const float*)d_in[2];
    const float* b_ih_f = (const float*)d_in[3];
    const float* W_hh_f = (const float*)d_in[4];
    const float* b_hh_f = (const float*)d_in[5];
    const float* W_ih_b = (const float*)d_in[6];
    const float* b_ih_b = (const float*)d_in[7];
    const float* W_hh_b = (const float*)d_in[8];
    const float* b_hh_b = (const float*)d_in[9];
    const float* W_out  = (const float*)d_in[10];
    const float* b_out  = (const float*)d_in[11];
    float* out = (float*)d_out;

    void *pe, *pxp, *pcomb, *pwih, *pwt;
    cudaGetSymbolAddress(&pe, g_emb);
    cudaGetSymbolAddress(&pxp, g_xp);
    cudaGetSymbolAddress(&pcomb, g_comb);
    cudaGetSymbolAddress(&pwih, g_wihp);
    cudaGetSymbolAddress(&pwt, g_wtp);
    __half*   emb  = (__half*)pe;
    __half*   xp   = (__half*)pxp;
    __half*   comb = (__half*)pcomb;
    uint32_t* wih  = (uint32_t*)pwih;
    uint32_t* wt   = (uint32_t*)pwt;

    cudaFuncSetAttribute(gemm_fp16, cudaFuncAttributeMaxDynamicSharedMemorySize, GSMEM);
    cudaFuncSetAttribute(lstm_kernel, cudaFuncAttributeMaxDynamicSharedMemorySize, LSMEM);

    // 0: embedding
    embed_kernel<<<MBS, 256>>>(x, embed);
    // 1: all weight prep (packs + W_hh transpose)
    prep_kernel<<<NPACKB + NTRB, 256>>>(W_ih_f, W_ih_b, W_out, W_hh_f, W_hh_b);
    // 2,3: input projections -> xp (fp16), 32x32 tiles
    gemm_fp16<<<32 * 32, 256, GSMEM>>>(emb, wih, b_ih_f, xp, MBS, G4, HH, 32, 1);
    gemm_fp16<<<32 * 32, 256, GSMEM>>>(emb, wih + 512L * G4, b_ih_b,
                                       xp + (size_t)MBS * G4, MBS, G4, HH, 32, 1);
    // 4: recurrence
    long long need = LOGITS + 4LL * BB * HH;
    int has_states = ((long long)out_size >= need) ? 1 : 0;
    lstm_kernel<<<128, 256, LSMEM>>>(b_hh_f, b_hh_b, out, has_states);
    // 5: output projection -> logits (fp32), 32 x 250 tiles
    gemm_fp16<<<32 * 250, 256, GSMEM>>>(comb, wt, b_out, out, MBS, VV, 2 * HH, 32, 0);
}

// round 16
// speedup vs baseline: 1.1993x; 1.0368x over previous
#include <cuda_runtime.h>
#include <cuda_fp16.h>
#include <math.h>
#include <stdint.h>

// ---------------------------------------------------------------------------
// Problem constants
// ---------------------------------------------------------------------------
#define BB   32
#define SS   128
#define HH   1024
#define G4   4096
#define VV   32000
#define MBS  4096                      // B*S
#define LOGITS 131072000LL             // B*S*V

// ---------------------------------------------------------------------------
// Device scratch
// ---------------------------------------------------------------------------
__device__ __half    g_emb [MBS * HH];             // 8 MB   [m][H] fp16
__device__ __half    g_xp  [2L * MBS * G4];        // 64 MB  [dir][m][4H] fp16
__device__ __half    g_comb[MBS * 2 * HH];         // 16 MB  [m][2H] fp16
__device__ uint32_t  g_wihp[2L * 512 * G4];        // 16 MB  packed fp16 pairs [k2][N]
__device__ uint32_t  g_wtp [1024L * VV];           // 128 MB packed fp16 pairs [k2][N]
__device__ uint32_t  g_whht[2L * G4 * 512];        // 16 MB  packed fp16 pairs [col][k2]
__device__ __half    g_h   [2 * 2 * BB * HH];      // [dir][pingpong][b][H]
__device__ unsigned  g_bar [2 * SS];               // per-dir barrier counters

// ---------------------------------------------------------------------------
// Helpers
// ---------------------------------------------------------------------------
__device__ __forceinline__ float4 ldcg4(const float4* p) {
    float4 v;
    asm volatile("ld.global.cg.v4.f32 {%0,%1,%2,%3}, [%4];"
                 : "=f"(v.x), "=f"(v.y), "=f"(v.z), "=f"(v.w) : "l"(p));
    return v;
}
__device__ __forceinline__ float sigm(float x) { return 1.f / (1.f + expf(-x)); }

__device__ __forceinline__ void mma_fp16(float* d, const uint32_t* a, const uint32_t* b) {
    asm volatile(
        "mma.sync.aligned.m16n8k16.row.col.f32.f16.f16.f32 "
        "{%0,%1,%2,%3},{%4,%5,%6,%7},{%8,%9},{%0,%1,%2,%3};"
        : "+f"(d[0]), "+f"(d[1]), "+f"(d[2]), "+f"(d[3])
        : "r"(a[0]), "r"(a[1]), "r"(a[2]), "r"(a[3]), "r"(b[0]), "r"(b[1]));
}

__device__ __forceinline__ void cpasync16(uint32_t dst, const void* src) {
    asm volatile("cp.async.cg.shared.global [%0], [%1], 16;" :: "r"(dst), "l"(src));
}
__device__ __forceinline__ uint32_t smem_u32(const void* p) {
    uint32_t a;
    asm("{ .reg .u64 t; cvta.to.shared.u64 t, %1; cvt.u32.u64 %0, t; }" : "=r"(a) : "l"(p));
    return a;
}

// ---------------------------------------------------------------------------
// Kernel: embedding gather -> fp16
// ---------------------------------------------------------------------------
__global__ void embed_kernel(const int* __restrict__ x, const float* __restrict__ embed) {
    int m = blockIdx.x;
    int idx = x[m];
    const float4* src = (const float4*)(embed + (size_t)idx * HH);
    __half2* dst = (__half2*)(g_emb + (size_t)m * HH);
    float4 v = src[threadIdx.x];
    dst[threadIdx.x * 2]     = __floats2half2_rn(v.x, v.y);
    dst[threadIdx.x * 2 + 1] = __floats2half2_rn(v.z, v.w);
}

// ---------------------------------------------------------------------------
// Kernel: all weight prep in ONE launch.
// ---------------------------------------------------------------------------
#define NPACKB 4096
#define NTRB   4096     // 2 dirs * 16 k2-tiles * 128 col-tiles

__global__ __launch_bounds__(256) void prep_kernel(
    const float* __restrict__ Wihf, const float* __restrict__ Wihb,
    const float* __restrict__ Wout,
    const float* __restrict__ Whhf, const float* __restrict__ Whhb)
{
    __shared__ float ts[64][33];
    int tid = threadIdx.x;

    if (blockIdx.x < NPACKB) {
        const size_t S1 = 512L * G4;
        const size_t S2 = 2 * S1;
        const size_t TOT = S2 + 1024L * VV;
        for (size_t i = (size_t)blockIdx.x * 256 + tid; i < TOT;
             i += (size_t)NPACKB * 256) {
            const float* src; uint32_t* dst; size_t off; int N;
            if (i < S1)       { src = Wihf; dst = g_wihp;      off = i;      N = G4; }
            else if (i < S2)  { src = Wihb; dst = g_wihp + S1; off = i - S1; N = G4; }
            else              { src = Wout; dst = g_wtp;       off = i - S2; N = VV; }
            size_t kk = off / (size_t)N, col = off - kk * N;
            __half2 h = __floats2half2_rn(src[(2 * kk) * (size_t)N + col],
                                          src[(2 * kk + 1) * (size_t)N + col]);
            dst[off] = *(uint32_t*)&h;
        }
    } else {
        int t   = blockIdx.x - NPACKB;
        int dir = t >> 11;
        int rem = t & 2047;
        int bx = rem & 127, by = rem >> 7;
        const float* src = dir ? Whhb : Whhf;
        int tx = tid & 31, ty = tid >> 5;
        int r0 = by * 64, c0 = bx * 32;
#pragma unroll
        for (int i = 0; i < 8; i++)
            ts[ty + 8 * i][tx] = src[(size_t)(r0 + ty + 8 * i) * G4 + c0 + tx];
        __syncthreads();
#pragma unroll
        for (int i = 0; i < 4; i++) {
            int colL = ty + 8 * i, k2L = tx;
            __half2 h = __floats2half2_rn(ts[2 * k2L][colL], ts[2 * k2L + 1][colL]);
            g_whht[(size_t)dir * G4 * 512 + (size_t)(c0 + colL) * 512 + by * 32 + k2L]
                = *(uint32_t*)&h;
        }
    }
}

// ---------------------------------------------------------------------------
// Kernel: fp16 GEMM  C[M,N] = A[M,K] @ B[K,N] + bias[N]   (B packed k-pairs)
// CTA tile 128x128, K-chunk 64, 3-stage cp.async, *128 thr* (4 warps as
// 2(wm) x 2(wn)), warp tile 64x64, 2 CTAs/SM, fragment double-buffering.
// launch_bounds(128,2) -> 256 regs/thread: fp32 acc (128) + dbl frags fit.
// smem traffic/chunk-pair: 192 KB / 2048 cyc = 94 B/cyc < 128 crossbar
// (R14 co-bound at 125 B/cyc with 64x32 tiles -> tensor/L1 serialized 52/48).
// Requires M%128==0, N%128==0, K%64==0.
// ---------------------------------------------------------------------------
#define STAGES 3
#define APITCH 36                 // words per A row (32 data + 4 pad)
#define BPITCH 136                // words per B row (128 data + 8 pad)
#define ASTG   (128 * APITCH)     // 4608 words
#define BSTG   (32 * BPITCH)      // 4352 words
#define STGW   (ASTG + BSTG)      // 8960 words / stage
#define GSMEM  (STAGES * STGW * 4)   // 107520 B -> 2 CTAs/SM

__global__ __launch_bounds__(128, 2) void gemm_fp16(
    const __half* __restrict__ A, const uint32_t* __restrict__ Bp,
    const float* __restrict__ bias, void* __restrict__ Cv,
    int M, int N, int K, int tiles_m, int half_out)
{
    extern __shared__ __align__(16) uint32_t smw[];
    uint32_t sb = smem_u32(smw);

    int tid = threadIdx.x, lane = tid & 31, warp = tid >> 5;
    int gid = lane >> 2, tq = lane & 3;
    int wm = warp >> 1, wn = warp & 1;

    int mt = blockIdx.x % tiles_m, nt = blockIdx.x / tiles_m;
    size_t m0 = (size_t)mt * 128, n0 = (size_t)nt * 128;
    int CH = K >> 6;

    // cp.async bases: A 1024 ops (8/thread, row-stride 16 between ops),
    //                 B 1024 ops (8/thread, k2-stride 4 between ops)
    const __half*   a_src = A + (m0 + (tid >> 3)) * (size_t)K + (tid & 7) * 8;
    const uint32_t* b_src = Bp + (size_t)(tid >> 5) * N + n0 + (tid & 31) * 4;
    uint32_t a_dst = ((tid >> 3) * APITCH + (tid & 7) * 4) * 4;
    uint32_t b_dst = (ASTG + (tid >> 5) * BPITCH + (tid & 31) * 4) * 4;

    float acc[4][8][4];
#pragma unroll
    for (int i = 0; i < 4; i++)
#pragma unroll
        for (int j = 0; j < 8; j++)
#pragma unroll
            for (int e = 0; e < 4; e++) acc[i][j][e] = 0.f;

#define ISSUE_CHUNK(c, s) {                                                   \
    uint32_t stb = sb + (uint32_t)(s) * (STGW * 4);                           \
    int k0h = (c) << 6;                                                       \
    size_t k0w = (size_t)((c) << 5) * N;                                      \
    _Pragma("unroll")                                                         \
    for (int i = 0; i < 8; i++)                                               \
        cpasync16(stb + a_dst + i * (16 * APITCH * 4),                        \
                  a_src + k0h + (size_t)(16 * i) * K);                        \
    _Pragma("unroll")                                                         \
    for (int i = 0; i < 8; i++)                                               \
        cpasync16(stb + b_dst + i * (4 * BPITCH * 4),                         \
                  b_src + k0w + (size_t)(4 * i) * N);                         \
}

#define LDFRAGS(buf, h) {                                                     \
    int kk = (h) * 8;                                                         \
    _Pragma("unroll")                                                         \
    for (int mi = 0; mi < 4; mi++) {                                          \
        int r = wm * 64 + mi * 16 + gid;                                      \
        af[buf][mi][0] = sA[r * APITCH + kk + tq];                            \
        af[buf][mi][1] = sA[(r + 8) * APITCH + kk + tq];                      \
        af[buf][mi][2] = sA[r * APITCH + kk + tq + 4];                        \
        af[buf][mi][3] = sA[(r + 8) * APITCH + kk + tq + 4];                  \
    }                                                                         \
    _Pragma("unroll")                                                         \
    for (int ni = 0; ni < 8; ni++) {                                          \
        int cc = wn * 64 + ni * 8 + gid;                                      \
        bf[buf][ni][0] = sB[(kk + tq) * BPITCH + cc];                         \
        bf[buf][ni][1] = sB[(kk + tq + 4) * BPITCH + cc];                     \
    }                                                                         \
}

    ISSUE_CHUNK(0, 0);
    asm volatile("cp.async.commit_group;");
    ISSUE_CHUNK(1, 1);
    asm volatile("cp.async.commit_group;");

    for (int c = 0; c < CH; c++) {
        asm volatile("cp.async.wait_group 1;");
        __syncthreads();
        if (c + 2 < CH) { int s = (c + 2) % STAGES; ISSUE_CHUNK(c + 2, s); }
        asm volatile("cp.async.commit_group;");

        const uint32_t* sA = smw + (c % STAGES) * STGW;
        const uint32_t* sB = sA + ASTG;

        uint32_t af[2][4][4], bf[2][8][2];
        LDFRAGS(0, 0);
#pragma unroll
        for (int h = 0; h < 4; h++) {
            int cb = h & 1;
            if (h < 3) LDFRAGS(cb ^ 1, h + 1);
#pragma unroll
            for (int mi = 0; mi < 4; mi++)
#pragma unroll
                for (int ni = 0; ni < 8; ni++)
                    mma_fp16(acc[mi][ni], af[cb][mi], bf[cb][ni]);
        }
    }

    // epilogue: add bias; store fp32 (logits) or fp16 (xp)
#pragma unroll
    for (int mi = 0; mi < 4; mi++) {
#pragma unroll
        for (int ni = 0; ni < 8; ni++) {
            size_t r = m0 + wm * 64 + mi * 16 + gid;
            size_t c = n0 + wn * 64 + ni * 8 + 2 * tq;
            float2 bv = *(const float2*)(bias + c);
            float v00 = acc[mi][ni][0] + bv.x, v01 = acc[mi][ni][1] + bv.y;
            float v10 = acc[mi][ni][2] + bv.x, v11 = acc[mi][ni][3] + bv.y;
            if (half_out) {
                __half* Ch = (__half*)Cv;
                *(__half2*)(Ch + r * (size_t)N + c)       = __floats2half2_rn(v00, v01);
                *(__half2*)(Ch + (r + 8) * (size_t)N + c) = __floats2half2_rn(v10, v11);
            } else {
                float* Cf = (float*)Cv;
                *(float2*)(Cf + r * (size_t)N + c)       = make_float2(v00, v01);
                *(float2*)(Cf + (r + 8) * (size_t)N + c) = make_float2(v10, v11);
            }
        }
    }
}

// ---------------------------------------------------------------------------
// Grid barrier: per-direction (64 CTAs), tight spin, self-resetting
// ---------------------------------------------------------------------------
__device__ __forceinline__ void gbar(int dir, int idx, int cid) {
    __threadfence();
    __syncthreads();
    if (threadIdx.x == 0) {
        unsigned* ctr = g_bar + dir * SS;
        unsigned a = atomicAdd(&ctr[idx], 1u);
        if (a + 1u < 64u) {
            while (((volatile unsigned*)ctr)[idx] < 64u) { }
        }
        if (cid == 0 && idx > 0) ((volatile unsigned*)ctr)[idx - 1] = 0u;
    }
    __syncthreads();
}

// ---------------------------------------------------------------------------
// Kernel: persistent bidirectional LSTM recurrence (unchanged from R14).
// ---------------------------------------------------------------------------
#define HPITCH 516
#define WPITCH 516
#define SW_WORDS (64 * WPITCH)
#define H_WORDS  (32 * HPITCH)
#define LSMEM ((SW_WORDS + H_WORDS + 32 * 68 + 512 + 64) * 4)

__global__ __launch_bounds__(256, 1) void lstm_kernel(
    const float* __restrict__ bhh_f, const float* __restrict__ bhh_b,
    float* __restrict__ out, int has_states)
{
    extern __shared__ uint32_t smu[];
    uint32_t* sW    = smu;                             // [64][WPITCH]
    uint32_t* h32   = smu + SW_WORDS;                  // [32][HPITCH]
    float* g_s      = (float*)(smu + SW_WORDS + H_WORDS);  // [32][68]
    float* c_s      = g_s + 32 * 68;                   // [512]
    float* bias_s   = c_s + 512;                       // [64]

    int dir = blockIdx.x >> 6;
    int cid = blockIdx.x & 63;
    int j0  = cid * 16;
    const float* bh = dir ? bhh_b : bhh_f;
    const __half* xp = g_xp + (size_t)dir * MBS * G4;
    __half* hbuf = g_h + (size_t)dir * 2 * BB * HH;

    int tid = threadIdx.x;
    int lane = tid & 31, warp = tid >> 5;
    int gid = lane >> 2, tq = lane & 3;
    int gate = warp & 3, kh = warp >> 2;

    {
        const uint32_t* Wt = g_whht + (size_t)dir * G4 * 512;
        for (int idx = tid; idx < 64 * 128; idx += 256) {
            int col = idx >> 7, seg = idx & 127;
            int gcol = (col >> 4) * 1024 + j0 + (col & 15);
            float4 v = *(const float4*)(Wt + (size_t)gcol * 512 + seg * 4);
            *(float4*)(sW + col * WPITCH + seg * 4) = v;
        }
    }
    for (int i = tid; i < 512; i += 256) c_s[i] = 0.f;
    if (tid < 64) bias_s[tid] = bh[(tid >> 4) * HH + j0 + (tid & 15)];
    for (int i = cid * 256 + tid; i < BB * HH; i += 64 * 256) hbuf[i] = __float2half(0.f);
    gbar(dir, 0, cid);

    int b0 = tid >> 4, jj = tid & 15;

    for (int step = 0; step < SS; step++) {
        int tseq = dir ? (SS - 1 - step) : step;
        int cur = step & 1, nxt = cur ^ 1;
        const __half* hg = hbuf + cur * BB * HH;

        __half xr0[4], xr1[4];
        {
            const __half* x0 = xp + (size_t)(b0 * SS + tseq) * G4 + j0 + jj;
            const __half* x1 = xp + (size_t)((b0 + 16) * SS + tseq) * G4 + j0 + jj;
#pragma unroll
            for (int q = 0; q < 4; q++) { xr0[q] = x0[q * 1024]; xr1[q] = x1[q * 1024]; }
        }

        for (int idx = tid; idx < 4096; idx += 256) {
            int r = idx >> 7, seg = idx & 127;
            float4 v = ldcg4((const float4*)hg + r * 128 + seg);
            *(float4*)(h32 + r * HPITCH + seg * 4) = v;
        }
        __syncthreads();

        float acc[2][2][4];
#pragma unroll
        for (int i = 0; i < 2; i++)
#pragma unroll
            for (int j = 0; j < 2; j++)
#pragma unroll
                for (int e = 0; e < 4; e++) acc[i][j][e] = 0.f;

        int colb = gate * 16 + gid;
        int kend = kh * 256 + 256;
#pragma unroll 8
        for (int kb2 = kh * 256; kb2 < kend; kb2 += 8) {
            uint32_t a[2][4];
#pragma unroll
            for (int mi = 0; mi < 2; mi++) {
                int r = mi * 16 + gid;
                a[mi][0] = h32[r * HPITCH + kb2 + tq];
                a[mi][1] = h32[(r + 8) * HPITCH + kb2 + tq];
                a[mi][2] = h32[r * HPITCH + kb2 + tq + 4];
                a[mi][3] = h32[(r + 8) * HPITCH + kb2 + tq + 4];
            }
#pragma unroll
            for (int ni = 0; ni < 2; ni++) {
                uint32_t bfr[2];
                const uint32_t* wc = sW + (colb + ni * 8) * WPITCH + kb2;
                bfr[0] = wc[tq];
                bfr[1] = wc[tq + 4];
                mma_fp16(acc[0][ni], a[0], bfr);
                mma_fp16(acc[1][ni], a[1], bfr);
            }
        }

        float* gp = g_s + gate * 16;
        if (kh == 0) {
#pragma unroll
            for (int mi = 0; mi < 2; mi++)
#pragma unroll
                for (int ni = 0; ni < 2; ni++) {
                    int r = mi * 16 + gid, c = ni * 8 + 2 * tq;
                    gp[r * 68 + c]           = acc[mi][ni][0];
                    gp[r * 68 + c + 1]       = acc[mi][ni][1];
                    gp[(r + 8) * 68 + c]     = acc[mi][ni][2];
                    gp[(r + 8) * 68 + c + 1] = acc[mi][ni][3];
                }
        }
        __syncthreads();
        if (kh == 1) {
#pragma unroll
            for (int mi = 0; mi < 2; mi++)
#pragma unroll
                for (int ni = 0; ni < 2; ni++) {
                    int r = mi * 16 + gid, c = ni * 8 + 2 * tq;
                    gp[r * 68 + c]           += acc[mi][ni][0];
                    gp[r * 68 + c + 1]       += acc[mi][ni][1];
                    gp[(r + 8) * 68 + c]     += acc[mi][ni][2];
                    gp[(r + 8) * 68 + c + 1] += acc[mi][ni][3];
                }
        }
        __syncthreads();

        __half* hn = hbuf + nxt * BB * HH;
#pragma unroll
        for (int half = 0; half < 2; half++) {
            int b = b0 + half * 16;
            int it = b * 16 + jj;
            const __half* xr = half ? xr1 : xr0;
            float gq[4];
#pragma unroll
            for (int q = 0; q < 4; q++)
                gq[q] = g_s[b * 68 + q * 16 + jj] + __half2float(xr[q]) + bias_s[q * 16 + jj];
            float iv = sigm(gq[0]);
            float fv = sigm(gq[1]);
            float gv = tanhf(gq[2]);
            float ov = sigm(gq[3]);
            float c = fv * c_s[it] + iv * gv;
            float h = ov * tanhf(c);
            c_s[it] = c;
            hn[b * HH + j0 + jj] = __float2half(h);
            g_comb[((size_t)(b * SS + tseq)) * 2 * HH + dir * HH + j0 + jj] = __float2half(h);
            if (has_states && step == SS - 1) {
                size_t base = LOGITS + (size_t)dir * 2 * BB * HH;
                out[base + b * HH + j0 + jj] = h;            // hT
                out[base + BB * HH + b * HH + j0 + jj] = c;  // cT
            }
        }
        if (step < SS - 1) gbar(dir, step + 1, cid);
        else __syncthreads();
    }
    if (cid == 0 && threadIdx.x == 0)
        ((volatile unsigned*)(g_bar + dir * SS))[SS - 1] = 0u;
}

// ---------------------------------------------------------------------------
// Launch
// ---------------------------------------------------------------------------
extern "C" void kernel_launch(void* const* d_in, const int* in_sizes, int n_in,
                              void* d_out, int out_size) {
    const int*   x      = (const int*)d_in[0];
    const float* embed  = (const float*)d_in[1];
    const float* W_ih_f = (const float*)d_in[2];
    const float* b_ih_f = (const float*)d_in[3];
    const float* W_hh_f = (const float*)d_in[4];
    const float* b_hh_f = (const float*)d_in[5];
    const float* W_ih_b = (const float*)d_in[6];
    const float* b_ih_b = (const float*)d_in[7];
    const float* W_hh_b = (const float*)d_in[8];
    const float* b_hh_b = (const float*)d_in[9];
    const float* W_out  = (const float*)d_in[10];
    const float* b_out  = (const float*)d_in[11];
    float* out = (float*)d_out;

    void *pe, *pxp, *pcomb, *pwih, *pwt;
    cudaGetSymbolAddress(&pe, g_emb);
    cudaGetSymbolAddress(&pxp, g_xp);
    cudaGetSymbolAddress(&pcomb, g_comb);
    cudaGetSymbolAddress(&pwih, g_wihp);
    cudaGetSymbolAddress(&pwt, g_wtp);
    __half*   emb  = (__half*)pe;
    __half*   xp   = (__half*)pxp;
    __half*   comb = (__half*)pcomb;
    uint32_t* wih  = (uint32_t*)pwih;
    uint32_t* wt   = (uint32_t*)pwt;

    cudaFuncSetAttribute(gemm_fp16, cudaFuncAttributeMaxDynamicSharedMemorySize, GSMEM);
    cudaFuncSetAttribute(lstm_kernel, cudaFuncAttributeMaxDynamicSharedMemorySize, LSMEM);

    // 0: embedding
    embed_kernel<<<MBS, 256>>>(x, embed);
    // 1: all weight prep (packs + W_hh transpose)
    prep_kernel<<<NPACKB + NTRB, 256>>>(W_ih_f, W_ih_b, W_out, W_hh_f, W_hh_b);
    // 2,3: input projections -> xp (fp16), 32x32 tiles
    gemm_fp16<<<32 * 32, 128, GSMEM>>>(emb, wih, b_ih_f, xp, MBS, G4, HH, 32, 1);
    gemm_fp16<<<32 * 32, 128, GSMEM>>>(emb, wih + 512L * G4, b_ih_b,
                                       xp + (size_t)MBS * G4, MBS, G4, HH, 32, 1);
    // 4: recurrence
    long long need = LOGITS + 4LL * BB * HH;
    int has_states = ((long long)out_size >= need) ? 1 : 0;
    lstm_kernel<<<128, 256, LSMEM>>>(b_hh_f, b_hh_b, out, has_states);
    // 5: output projection -> logits (fp32), 32 x 250 tiles
    gemm_fp16<<<32 * 250, 128, GSMEM>>>(comb, wt, b_out, out, MBS, VV, 2 * HH, 32, 0);
}